// round 6
// baseline (speedup 1.0000x reference)
#include <cuda_runtime.h>
#include <cstdint>

// Problem constants
#define N_V   50000
#define R_    5
#define A_    8
#define RA    40
#define C_    64
#define KX    2560            // RA * C
#define KTOT  2624            // KX + C (center fold appended)
#define NCOL  512             // O * T
#define KT_N  82              // KTOT / 32
#define MB_N  391             // ceil(50048 / 128)

// B in MMA-fragment layout: per (col-tile nb of 128, k-chunk kt of 32): 4096 floats.
__device__ float g_Bfrag[(size_t)4 * KT_N * 4096];      // 5.4 MB
__device__ float g_biasExt[NCOL];

__device__ __forceinline__ float tf32r(float x) {
    uint32_t u;
    asm("cvt.rna.tf32.f32 %0, %1;" : "=r"(u) : "f"(x));
    return __uint_as_float(u);
}
__device__ __forceinline__ uint32_t smem_u32(const void* p) {
    uint32_t a;
    asm("{ .reg .u64 t; cvta.to.shared.u64 t, %1; cvt.u32.u64 %0, t; }" : "=r"(a) : "l"(p));
    return a;
}

// ---------------------------------------------------------------------------
// K0: fold interpolation prior + rotation + center weights into B-fragments.
//   Weff[o,t,m,c] = sum_{r,a} coeff[r,a,m] * W[t, r, (a+o)%A, c]
// B fragment layout within a (nb, kt) 16KB chunk:
//   idx = ((NT*4+kk)*32 + gn*4 + t4)*2 + r
// ---------------------------------------------------------------------------
__device__ __forceinline__ size_t bfrag_addr(int k, int j) {
    int kt = k >> 5, kl = k & 31;
    int kk = kl >> 3, wi = kl & 7, t4 = wi & 3, r = wi >> 2;
    int nb = j >> 7, nl = j & 127;
    int NT = nl >> 3, gn = nl & 7;
    return ((size_t)(nb * KT_N + kt)) * 4096 +
           (size_t)(((NT * 4 + kk) * 32 + gn * 4 + t4) * 2 + r);
}

__global__ void build_B_kernel(const float* __restrict__ nw,
                               const float* __restrict__ cw,
                               const float* __restrict__ bias,
                               const float* __restrict__ coeff)
{
    int j = blockIdx.x;            // 0..511
    int o = j >> 6;
    int t = j & 63;
    int c = threadIdx.x;           // 64 threads

    __shared__ float s_coeff[R_ * A_ * RA];
    for (int i = c; i < R_ * A_ * RA; i += 64) s_coeff[i] = coeff[i];
    __syncthreads();

    float wv[R_][A_];
    #pragma unroll
    for (int r = 0; r < R_; r++)
        #pragma unroll
        for (int a = 0; a < A_; a++)
            wv[r][a] = nw[(((size_t)t * R_ + r) * A_ + ((a + o) & 7)) * C_ + c];

    for (int m = 0; m < RA; m++) {
        float acc = 0.f;
        #pragma unroll
        for (int r = 0; r < R_; r++)
            #pragma unroll
            for (int a = 0; a < A_; a++)
                acc += s_coeff[(r * A_ + a) * RA + m] * wv[r][a];
        g_Bfrag[bfrag_addr(m * C_ + c, j)] = tf32r(acc);
    }
    g_Bfrag[bfrag_addr(KX + c, j)] = tf32r(cw[t * C_ + c]);
    if (c == 0) g_biasExt[j] = bias[t];
}

// ---------------------------------------------------------------------------
// Fused gather + tf32 mma.sync GEMM + bias + relu.
// BM=128, BN=256, BK=32 chunks (82). 256 threads = 8 warps (2m x 4n),
// warp tile 64x64. A: gathered in-kernel into fragment-layout smem
// (3 rotating 16KB buffers). B: cp.async from L2-hot g_Bfrag (3 x 32KB).
// Bary staged per-m into 3 rotating smem buffers, 2 chunks ahead.
// ---------------------------------------------------------------------------
#define A_OFF_B    0
#define B_OFF_B    49152
#define BARY_OFF_B 147456
#define SMEM_TOTAL 156672     // + bary 3*3072

__device__ __forceinline__ void mma_tf32(float* c, float a0, float a1, float a2, float a3,
                                         float b0, float b1)
{
    asm volatile(
        "mma.sync.aligned.m16n8k8.row.col.f32.tf32.tf32.f32 "
        "{%0,%1,%2,%3}, {%4,%5,%6,%7}, {%8,%9}, {%0,%1,%2,%3};\n"
        : "+f"(c[0]), "+f"(c[1]), "+f"(c[2]), "+f"(c[3])
        : "r"(__float_as_uint(a0)), "r"(__float_as_uint(a1)),
          "r"(__float_as_uint(a2)), "r"(__float_as_uint(a3)),
          "r"(__float_as_uint(b0)), "r"(__float_as_uint(b1)));
}
__device__ __forceinline__ void cp16(uint32_t s, const void* g) {
    asm volatile("cp.async.cg.shared.global [%0], [%1], 16;" :: "r"(s), "l"(g));
}

__global__ __launch_bounds__(256, 1)
void fused_gemm_kernel(const float* __restrict__ ms,
                       const float* __restrict__ bary,
                       float* __restrict__ out)
{
    extern __shared__ __align__(16) char smem[];
    float* smf    = (float*)smem;
    uint32_t sbase = smem_u32(smem);

    int tid  = threadIdx.x;
    int warp = tid >> 5;
    int ln   = tid & 31;
    int wm   = warp >> 2;          // 0..1
    int wn   = warp & 3;           // 0..3
    int mb   = blockIdx.y;
    int bx   = blockIdx.x;         // 0..1

    // ---- helpers as lambdas ----
    auto stage_bary = [&](int m) {
        if (tid < 128) {
            int n = mb * 128 + tid;
            float* dst = smf + (BARY_OFF_B / 4) + (m % 3) * 768 + tid * 6;
            if (n < N_V) {
                const float* src = bary + ((size_t)n * RA + m) * 6;
                float2 p0 = *(const float2*)(src);
                float2 p1 = *(const float2*)(src + 2);
                float2 p2 = *(const float2*)(src + 4);
                dst[0] = p0.x; dst[1] = p0.y;
                dst[2] = p1.x; dst[3] = p1.y;
                dst[4] = p2.x; dst[5] = p2.y;
            } else {
                dst[0] = 0.f; dst[1] = 0.f; dst[2] = 0.f;
                dst[3] = 0.f; dst[4] = 0.f; dst[5] = 0.f;
            }
        }
    };

    auto gather_chunk = [&](int c) {
        int m  = c >> 1;
        int cb = (c & 1) * 32;
        float4* Adst = (float4*)(smf + (c % 3) * 4096);
        if (m < RA) {
            const float* sby = smf + (BARY_OFF_B / 4) + (m % 3) * 768;
            #pragma unroll
            for (int i = 0; i < 4; i++) {
                int q  = tid + i * 256;
                int t4 = q & 3, gl = (q >> 2) & 7, kk = (q >> 5) & 3, MT = q >> 7;
                int lr = MT * 16 + gl;
                int k0 = cb + kk * 8 + t4;
                const float* b0 = sby + lr * 6;
                const float* b1 = sby + (lr + 8) * 6;
                int   i00 = (int)b0[0]; float w00 = b0[1];
                int   i01 = (int)b0[2]; float w01 = b0[3];
                int   i02 = (int)b0[4]; float w02 = b0[5];
                int   i10 = (int)b1[0]; float w10 = b1[1];
                int   i11 = (int)b1[2]; float w11 = b1[3];
                int   i12 = (int)b1[4]; float w12 = b1[5];
                const float* r00 = ms + (size_t)i00 * C_;
                const float* r01 = ms + (size_t)i01 * C_;
                const float* r02 = ms + (size_t)i02 * C_;
                const float* r10 = ms + (size_t)i10 * C_;
                const float* r11 = ms + (size_t)i11 * C_;
                const float* r12 = ms + (size_t)i12 * C_;
                float v0 = w00 * __ldg(r00 + k0) + w01 * __ldg(r01 + k0) + w02 * __ldg(r02 + k0);
                float v1 = w00 * __ldg(r00 + k0 + 4) + w01 * __ldg(r01 + k0 + 4) + w02 * __ldg(r02 + k0 + 4);
                float v2 = w10 * __ldg(r10 + k0) + w11 * __ldg(r11 + k0) + w12 * __ldg(r12 + k0);
                float v3 = w10 * __ldg(r10 + k0 + 4) + w11 * __ldg(r11 + k0 + 4) + w12 * __ldg(r12 + k0 + 4);
                Adst[q] = make_float4(tf32r(v0), tf32r(v1), tf32r(v2), tf32r(v3));
            }
        } else {
            // center chunk: X[n, KX + c] = ms[n, c]
            #pragma unroll
            for (int i = 0; i < 4; i++) {
                int q  = tid + i * 256;
                int t4 = q & 3, gl = (q >> 2) & 7, kk = (q >> 5) & 3, MT = q >> 7;
                int n0 = mb * 128 + MT * 16 + gl;
                int n1 = n0 + 8;
                int k0 = cb + kk * 8 + t4;
                float v0 = (n0 < N_V) ? __ldg(ms + (size_t)n0 * C_ + k0) : 0.f;
                float v1 = (n0 < N_V) ? __ldg(ms + (size_t)n0 * C_ + k0 + 4) : 0.f;
                float v2 = (n1 < N_V) ? __ldg(ms + (size_t)n1 * C_ + k0) : 0.f;
                float v3 = (n1 < N_V) ? __ldg(ms + (size_t)n1 * C_ + k0 + 4) : 0.f;
                Adst[q] = make_float4(tf32r(v0), tf32r(v1), tf32r(v2), tf32r(v3));
            }
        }
    };

    auto issueB = [&](int c) {
        uint32_t dst = sbase + B_OFF_B + (uint32_t)(c % 3) * 32768;
        const float* s0 = g_Bfrag + ((size_t)(bx * 2 + 0) * KT_N + c) * 4096;
        const float* s1 = g_Bfrag + ((size_t)(bx * 2 + 1) * KT_N + c) * 4096;
        #pragma unroll
        for (int i = 0; i < 4; i++)
            cp16(dst + (tid + i * 256) * 16, s0 + (tid + i * 256) * 4);
        #pragma unroll
        for (int i = 0; i < 4; i++)
            cp16(dst + 16384 + (tid + i * 256) * 16, s1 + (tid + i * 256) * 4);
    };

    // ---- prologue ----
    stage_bary(0);
    stage_bary(1);
    __syncthreads();
    gather_chunk(0);
    issueB(0);
    asm volatile("cp.async.commit_group;" ::: "memory");
    __syncthreads();

    float acc[4][8][4];
    #pragma unroll
    for (int mt = 0; mt < 4; mt++)
        #pragma unroll
        for (int nt = 0; nt < 8; nt++)
            #pragma unroll
            for (int i = 0; i < 4; i++) acc[mt][nt][i] = 0.f;

    // ---- main loop ----
    for (int s = 0; s < KT_N; s++) {
        if (s & 1) {
            int mt_ = (s + 3) >> 1;
            if (mt_ < RA) stage_bary(mt_);
        }
        if (s + 1 < KT_N) {
            gather_chunk(s + 1);
            issueB(s + 1);
            asm volatile("cp.async.commit_group;" ::: "memory");
            asm volatile("cp.async.wait_group 1;" ::: "memory");
        } else {
            asm volatile("cp.async.wait_group 0;" ::: "memory");
        }
        __syncthreads();

        uint32_t bufA = sbase + (uint32_t)(s % 3) * 16384;
        uint32_t bufB = sbase + B_OFF_B + (uint32_t)(s % 3) * 32768
                        + (uint32_t)(wn >> 1) * 16384;

        #pragma unroll
        for (int kk = 0; kk < 4; kk++) {
            float4 af[4];
            float2 bf[8];
            #pragma unroll
            for (int mt = 0; mt < 4; mt++) {
                uint32_t a = bufA + ((((wm * 4 + mt) * 4 + kk) * 32 + ln) * 16);
                asm volatile("ld.shared.v4.f32 {%0,%1,%2,%3}, [%4];"
                             : "=f"(af[mt].x), "=f"(af[mt].y), "=f"(af[mt].z), "=f"(af[mt].w)
                             : "r"(a));
            }
            #pragma unroll
            for (int nt = 0; nt < 8; nt++) {
                uint32_t b = bufB + (((((wn & 1) * 8 + nt) * 4 + kk) * 32 + ln) * 8);
                asm volatile("ld.shared.v2.f32 {%0,%1}, [%2];"
                             : "=f"(bf[nt].x), "=f"(bf[nt].y) : "r"(b));
            }
            #pragma unroll
            for (int mt = 0; mt < 4; mt++)
                #pragma unroll
                for (int nt = 0; nt < 8; nt++)
                    // A frag float4 = (a0, a2, a1, a3)
                    mma_tf32(acc[mt][nt], af[mt].x, af[mt].z, af[mt].y, af[mt].w,
                             bf[nt].x, bf[nt].y);
        }
    }

    // ---- epilogue: bias + relu ----
    int g  = ln >> 2;
    int t4 = ln & 3;
    #pragma unroll
    for (int nt = 0; nt < 8; nt++) {
        int col = bx * 256 + wn * 64 + nt * 8 + t4 * 2;
        float b0 = g_biasExt[col];
        float b1 = g_biasExt[col + 1];
        #pragma unroll
        for (int mt = 0; mt < 4; mt++) {
            int row0 = mb * 128 + wm * 64 + mt * 16 + g;
            float v0 = acc[mt][nt][0] + b0;
            float v1 = acc[mt][nt][1] + b1;
            float v2 = acc[mt][nt][2] + b0;
            float v3 = acc[mt][nt][3] + b1;
            v0 = v0 > 0.f ? v0 : 0.f;
            v1 = v1 > 0.f ? v1 : 0.f;
            v2 = v2 > 0.f ? v2 : 0.f;
            v3 = v3 > 0.f ? v3 : 0.f;
            if (row0 < N_V)
                *(float2*)(out + (size_t)row0 * NCOL + col) = make_float2(v0, v1);
            if (row0 + 8 < N_V)
                *(float2*)(out + (size_t)(row0 + 8) * NCOL + col) = make_float2(v2, v3);
        }
    }
}

// ---------------------------------------------------------------------------
// Launch
// Inputs: mesh_signal, bary_coordinates, neighbor_weights, center_weights,
//         bias, interp_coeff
// ---------------------------------------------------------------------------
extern "C" void kernel_launch(void* const* d_in, const int* in_sizes, int n_in,
                              void* d_out, int out_size)
{
    const float* ms    = (const float*)d_in[0];
    const float* bary  = (const float*)d_in[1];
    const float* nw    = (const float*)d_in[2];
    const float* cw    = (const float*)d_in[3];
    const float* bias  = (const float*)d_in[4];
    const float* coeff = (const float*)d_in[5];
    float* out = (float*)d_out;

    cudaFuncSetAttribute(fused_gemm_kernel,
                         cudaFuncAttributeMaxDynamicSharedMemorySize, SMEM_TOTAL);

    build_B_kernel<<<NCOL, 64>>>(nw, cw, bias, coeff);

    dim3 grid(2, MB_N);
    fused_gemm_kernel<<<grid, 256, SMEM_TOTAL>>>(ms, bary, out);
}

// round 7
// speedup vs baseline: 1.7415x; 1.7415x over previous
#include <cuda_runtime.h>
#include <cstdint>

// Problem constants
#define N_V   50000
#define R_    5
#define A_    8
#define RA    40
#define C_    64
#define KX    2560            // RA * C
#define KTOT  2624            // KX + C (center fold appended)
#define NCOL  512             // O * T
#define KT_N  82              // KTOT / 32
#define MB_N  391             // ceil(50048 / 128)

// Scratch (static device arrays — no cudaMalloc allowed)
__device__ float g_Afrag[(size_t)MB_N * KT_N * 4096];   // ~513 MB
__device__ float g_Bfrag[(size_t)4 * KT_N * 4096];      // 5.4 MB
__device__ float g_biasExt[NCOL];

__device__ __forceinline__ float tf32r(float x) {
    uint32_t u;
    asm("cvt.rna.tf32.f32 %0, %1;" : "=r"(u) : "f"(x));
    return __uint_as_float(u);
}
__device__ __forceinline__ uint32_t smem_u32(const void* p) {
    uint32_t a;
    asm("{ .reg .u64 t; cvta.to.shared.u64 t, %1; cvt.u32.u64 %0, t; }" : "=r"(a) : "l"(p));
    return a;
}

// ---------------------------------------------------------------------------
// K0: fold interpolation prior + rotation + center weights into B-fragments.
// B fragment layout within a (nb, kt) 16KB chunk:
//   idx = ((NT*4+kk)*32 + gn*4 + t4)*2 + r
// ---------------------------------------------------------------------------
__device__ __forceinline__ size_t bfrag_addr(int k, int j) {
    int kt = k >> 5, kl = k & 31;
    int kk = kl >> 3, wi = kl & 7, t4 = wi & 3, r = wi >> 2;
    int nb = j >> 7, nl = j & 127;
    int NT = nl >> 3, gn = nl & 7;
    return ((size_t)(nb * KT_N + kt)) * 4096 +
           (size_t)(((NT * 4 + kk) * 32 + gn * 4 + t4) * 2 + r);
}

__global__ void build_B_kernel(const float* __restrict__ nw,
                               const float* __restrict__ cw,
                               const float* __restrict__ bias,
                               const float* __restrict__ coeff)
{
    int j = blockIdx.x;            // 0..511
    int o = j >> 6;
    int t = j & 63;
    int c = threadIdx.x;           // 64 threads

    __shared__ float s_coeff[R_ * A_ * RA];
    for (int i = c; i < R_ * A_ * RA; i += 64) s_coeff[i] = coeff[i];
    __syncthreads();

    float wv[R_][A_];
    #pragma unroll
    for (int r = 0; r < R_; r++)
        #pragma unroll
        for (int a = 0; a < A_; a++)
            wv[r][a] = nw[(((size_t)t * R_ + r) * A_ + ((a + o) & 7)) * C_ + c];

    for (int m = 0; m < RA; m++) {
        float acc = 0.f;
        #pragma unroll
        for (int r = 0; r < R_; r++)
            #pragma unroll
            for (int a = 0; a < A_; a++)
                acc += s_coeff[(r * A_ + a) * RA + m] * wv[r][a];
        g_Bfrag[bfrag_addr(m * C_ + c, j)] = tf32r(acc);
    }
    g_Bfrag[bfrag_addr(KX + c, j)] = tf32r(cw[t * C_ + c]);
    if (c == 0) g_biasExt[j] = bias[t];
}

// ---------------------------------------------------------------------------
// K1: barycentric gather + interpolation, written directly as A-fragments.
// One block per vertex PAIR (n, n+8). Coalesced lane=channel gathers.
// ---------------------------------------------------------------------------
__global__ __launch_bounds__(256)
void build_X_kernel(const float* __restrict__ ms,
                    const float* __restrict__ bary)
{
    int bp = blockIdx.x;
    int mb = bp >> 6;
    int q  = bp & 63;
    int MT = q >> 3;
    int gl = q & 7;
    int n0 = mb * 128 + MT * 16 + gl;

    __shared__ float s_row[2][KTOT];
    __shared__ float sb[240];
    int tid = threadIdx.x;

    #pragma unroll
    for (int v = 0; v < 2; v++) {
        int n = n0 + 8 * v;
        if (n < N_V) {
            if (tid < 240) sb[tid] = bary[(size_t)n * 240 + tid];
            __syncthreads();
            int g4 = tid >> 6;
            int c  = tid & 63;
            #pragma unroll
            for (int it = 0; it < 10; it++) {
                int m  = it * 4 + g4;
                int i0 = (int)sb[m * 6 + 0]; float w0 = sb[m * 6 + 1];
                int i1 = (int)sb[m * 6 + 2]; float w1 = sb[m * 6 + 3];
                int i2 = (int)sb[m * 6 + 4]; float w2 = sb[m * 6 + 5];
                s_row[v][m * C_ + c] = w0 * ms[(size_t)i0 * C_ + c]
                                     + w1 * ms[(size_t)i1 * C_ + c]
                                     + w2 * ms[(size_t)i2 * C_ + c];
            }
            if (g4 == 0) s_row[v][KX + c] = ms[(size_t)n * C_ + c];
        } else {
            for (int i = tid; i < KTOT; i += 256) s_row[v][i] = 0.f;
        }
        __syncthreads();
    }

    for (int w = tid; w < KT_N * 16; w += 256) {
        int kt = w >> 4;
        int kk = (w >> 2) & 3;
        int t4 = w & 3;
        int k  = kt * 32 + kk * 8 + t4;
        float4 val = make_float4(tf32r(s_row[0][k]), tf32r(s_row[0][k + 4]),
                                 tf32r(s_row[1][k]), tf32r(s_row[1][k + 4]));
        ((float4*)(g_Afrag + ((size_t)mb * KT_N + kt) * 4096))
            [(MT * 4 + kk) * 32 + gl * 4 + t4] = val;
    }
}

// ---------------------------------------------------------------------------
// K2: tf32 mma.sync GEMM + bias + relu.
// BM=128, BN=256, BK=32. 512 threads = 16 warps (2m x 8n), warp tile 64x32.
// 3-stage cp.async pipeline (48KB/stage). 4 warps/SMSP for latency hiding.
// ---------------------------------------------------------------------------
__device__ __forceinline__ void mma_tf32(float* c, float a0, float a1, float a2, float a3,
                                         float b0, float b1)
{
    asm volatile(
        "mma.sync.aligned.m16n8k8.row.col.f32.tf32.tf32.f32 "
        "{%0,%1,%2,%3}, {%4,%5,%6,%7}, {%8,%9}, {%0,%1,%2,%3};\n"
        : "+f"(c[0]), "+f"(c[1]), "+f"(c[2]), "+f"(c[3])
        : "r"(__float_as_uint(a0)), "r"(__float_as_uint(a1)),
          "r"(__float_as_uint(a2)), "r"(__float_as_uint(a3)),
          "r"(__float_as_uint(b0)), "r"(__float_as_uint(b1)));
}
__device__ __forceinline__ void cp16(uint32_t s, const void* g) {
    asm volatile("cp.async.cg.shared.global [%0], [%1], 16;" :: "r"(s), "l"(g));
}

#define STAGE_BYTES 49152      // 16KB A + 32KB B
#define SMEM_TOTAL  (3 * STAGE_BYTES)   // 144KB

__global__ __launch_bounds__(512, 1)
void gemm_relu_kernel(float* __restrict__ out)
{
    extern __shared__ float smemf[];
    uint32_t sbase = smem_u32(smemf);

    int tid  = threadIdx.x;
    int warp = tid >> 5;
    int ln   = tid & 31;
    int wm   = warp >> 3;          // 0..1  (m half, 64 rows)
    int wn   = warp & 7;           // 0..7  (n slice, 32 cols)
    int mb   = blockIdx.y;
    int bx   = blockIdx.x;         // 0..1  (n half of 256)

    const float* Ag  = g_Afrag + (size_t)mb * KT_N * 4096;
    const float* Bg0 = g_Bfrag + (size_t)(bx * 2 + 0) * KT_N * 4096;
    const float* Bg1 = g_Bfrag + (size_t)(bx * 2 + 1) * KT_N * 4096;

    auto issue = [&](int s) {
        uint32_t dst = sbase + (uint32_t)(s % 3) * STAGE_BYTES;
        const float* As = Ag + (size_t)s * 4096;
        #pragma unroll
        for (int i = 0; i < 2; i++)
            cp16(dst + (tid + i * 512) * 16, As + (tid + i * 512) * 4);
        const float* Bs0 = Bg0 + (size_t)s * 4096;
        const float* Bs1 = Bg1 + (size_t)s * 4096;
        #pragma unroll
        for (int i = 0; i < 2; i++)
            cp16(dst + 16384 + (tid + i * 512) * 16, Bs0 + (tid + i * 512) * 4);
        #pragma unroll
        for (int i = 0; i < 2; i++)
            cp16(dst + 32768 + (tid + i * 512) * 16, Bs1 + (tid + i * 512) * 4);
    };

    issue(0);
    asm volatile("cp.async.commit_group;" ::: "memory");
    issue(1);
    asm volatile("cp.async.commit_group;" ::: "memory");

    float acc[4][4][4];
    #pragma unroll
    for (int mt = 0; mt < 4; mt++)
        #pragma unroll
        for (int nt = 0; nt < 4; nt++)
            #pragma unroll
            for (int i = 0; i < 4; i++) acc[mt][nt][i] = 0.f;

    for (int kt = 0; kt < KT_N; kt++) {
        asm volatile("cp.async.wait_group 1;" ::: "memory");
        __syncthreads();

        if (kt + 2 < KT_N) issue(kt + 2);
        asm volatile("cp.async.commit_group;" ::: "memory");

        uint32_t bufA = sbase + (uint32_t)(kt % 3) * STAGE_BYTES;
        uint32_t bufB = bufA + 16384 + (uint32_t)(wn >> 2) * 16384;

        #pragma unroll
        for (int kk = 0; kk < 4; kk++) {
            float4 af[4];
            float2 bf[4];
            #pragma unroll
            for (int mt = 0; mt < 4; mt++) {
                uint32_t a = bufA + ((((wm * 4 + mt) * 4 + kk) * 32 + ln) * 16);
                asm volatile("ld.shared.v4.f32 {%0,%1,%2,%3}, [%4];"
                             : "=f"(af[mt].x), "=f"(af[mt].y), "=f"(af[mt].z), "=f"(af[mt].w)
                             : "r"(a));
            }
            #pragma unroll
            for (int nt = 0; nt < 4; nt++) {
                int NT = (wn & 3) * 4 + nt;
                uint32_t b = bufB + (((NT * 4 + kk) * 32 + ln) * 8);
                asm volatile("ld.shared.v2.f32 {%0,%1}, [%2];"
                             : "=f"(bf[nt].x), "=f"(bf[nt].y) : "r"(b));
            }
            #pragma unroll
            for (int mt = 0; mt < 4; mt++)
                #pragma unroll
                for (int nt = 0; nt < 4; nt++)
                    // A frag float4 = (a0, a2, a1, a3)
                    mma_tf32(acc[mt][nt], af[mt].x, af[mt].z, af[mt].y, af[mt].w,
                             bf[nt].x, bf[nt].y);
        }
        __syncthreads();
    }

    // epilogue: bias + relu
    int g  = ln >> 2;
    int t4 = ln & 3;
    #pragma unroll
    for (int nt = 0; nt < 4; nt++) {
        int col = bx * 256 + (wn >> 2) * 128 + (wn & 3) * 32 + nt * 8 + t4 * 2;
        float b0 = g_biasExt[col];
        float b1 = g_biasExt[col + 1];
        #pragma unroll
        for (int mt = 0; mt < 4; mt++) {
            int row0 = mb * 128 + wm * 64 + mt * 16 + g;
            float v0 = acc[mt][nt][0] + b0;
            float v1 = acc[mt][nt][1] + b1;
            float v2 = acc[mt][nt][2] + b0;
            float v3 = acc[mt][nt][3] + b1;
            v0 = v0 > 0.f ? v0 : 0.f;
            v1 = v1 > 0.f ? v1 : 0.f;
            v2 = v2 > 0.f ? v2 : 0.f;
            v3 = v3 > 0.f ? v3 : 0.f;
            if (row0 < N_V)
                *(float2*)(out + (size_t)row0 * NCOL + col) = make_float2(v0, v1);
            if (row0 + 8 < N_V)
                *(float2*)(out + (size_t)(row0 + 8) * NCOL + col) = make_float2(v2, v3);
        }
    }
}

// ---------------------------------------------------------------------------
// Launch
// Inputs: mesh_signal, bary_coordinates, neighbor_weights, center_weights,
//         bias, interp_coeff
// ---------------------------------------------------------------------------
extern "C" void kernel_launch(void* const* d_in, const int* in_sizes, int n_in,
                              void* d_out, int out_size)
{
    const float* ms    = (const float*)d_in[0];
    const float* bary  = (const float*)d_in[1];
    const float* nw    = (const float*)d_in[2];
    const float* cw    = (const float*)d_in[3];
    const float* bias  = (const float*)d_in[4];
    const float* coeff = (const float*)d_in[5];
    float* out = (float*)d_out;

    cudaFuncSetAttribute(gemm_relu_kernel,
                         cudaFuncAttributeMaxDynamicSharedMemorySize, SMEM_TOTAL);

    build_B_kernel<<<NCOL, 64>>>(nw, cw, bias, coeff);
    build_X_kernel<<<MB_N * 64, 256>>>(ms, bary);

    dim3 grid(2, MB_N);
    gemm_relu_kernel<<<grid, 512, SMEM_TOTAL>>>(out);
}